// round 2
// baseline (speedup 1.0000x reference)
#include <cuda_runtime.h>

// Problem constants
#define BB 1024
#define TT 512
#define II 64
#define HH 32
#define N_ROWS (BB * TT)          // 524288
#define OUT_OFFSET (BB * TT)      // h_last written after outs

// Scratch: x_proj in [T, B, H] layout so the recurrence reads coalesced 128B per (t,b)
__device__ float g_xp[TT * BB * HH];

// Packed fp32x2 FMA (Blackwell): d = a*b + c elementwise on pairs
__device__ __forceinline__ float2 ffma2(float2 a, float2 b, float2 c) {
    union U { float2 f; unsigned long long u; };
    U ua, ub, uc, ud;
    ua.f = a; ub.f = b; uc.f = c;
    asm("fma.rn.f32x2 %0, %1, %2, %3;"
        : "=l"(ud.u) : "l"(ua.u), "l"(ub.u), "l"(uc.u));
    return ud.f;
}

// ---------------------------------------------------------------------------
// Kernel 1: x_proj[t][b][h] = b_ih[h] + sum_k x[b][t][k] * W_ih[h][k]
// One warp per (b,t) row. Lane j owns output column j; K=64 vectorized as
// 32 f32x2 pairs with W_ih pairs pre-loaded in registers. x row staged to
// smem once (1 LDG.64/lane) and read back as broadcast LDS.64.
// ---------------------------------------------------------------------------
__global__ __launch_bounds__(256) void xproj_kernel(
    const float* __restrict__ x,
    const float* __restrict__ W_ih,
    const float* __restrict__ b_ih)
{
    __shared__ __align__(16) float2 sx[8][2][32];   // 8 warps, double buffered

    const int lane = threadIdx.x & 31;
    const int wid  = threadIdx.x >> 5;
    const int gw   = (blockIdx.x * blockDim.x + threadIdx.x) >> 5;
    const int nw   = (gridDim.x * blockDim.x) >> 5;

    // Lane j holds W_ih row j as 32 packed pairs
    float2 w2[32];
    const float2* wr = reinterpret_cast<const float2*>(W_ih + lane * II);
#pragma unroll
    for (int m = 0; m < 32; ++m) w2[m] = wr[m];
    const float bias = b_ih[lane];

    int buf = 0;
    for (int r = gw; r < N_ROWS; r += nw) {
        const int t = r >> 10;          // r = t*1024 + b
        const int b = r & 1023;

        const float2* xr =
            reinterpret_cast<const float2*>(x + ((size_t)b * TT + t) * II);
        sx[wid][buf][lane] = xr[lane];  // pair {x[2*lane], x[2*lane+1]}
        __syncwarp();

        float2 a0 = {0.f, 0.f}, a1 = {0.f, 0.f}, a2 = {0.f, 0.f}, a3 = {0.f, 0.f};
        const float2* sp = sx[wid][buf];
#pragma unroll
        for (int m = 0; m < 32; m += 4) {
            a0 = ffma2(sp[m + 0], w2[m + 0], a0);
            a1 = ffma2(sp[m + 1], w2[m + 1], a1);
            a2 = ffma2(sp[m + 2], w2[m + 2], a2);
            a3 = ffma2(sp[m + 3], w2[m + 3], a3);
        }
        float v = ((a0.x + a1.x) + (a0.y + a1.y)) +
                  ((a2.x + a3.x) + (a2.y + a3.y)) + bias;

        g_xp[(size_t)t * (BB * HH) + b * HH + lane] = v;   // coalesced 128B
        buf ^= 1;
    }
}

// ---------------------------------------------------------------------------
// Kernel 2: sequential recurrence. One warp per batch element.
// Lane j owns h[j]; h replicated via smem double buffer (broadcast LDS.64,
// one __syncwarp per step). Per-step output dot is stashed into a 33-padded
// smem transpose and flushed as a coalesced 128B store every 32 steps.
// ---------------------------------------------------------------------------
__global__ __launch_bounds__(128) void rnn_kernel(
    const float* __restrict__ h0,
    const float* __restrict__ W_hh,
    const float* __restrict__ b_hh,
    const float* __restrict__ W_out,
    const float* __restrict__ b_out,
    float* __restrict__ out)
{
    __shared__ __align__(16) float hs[4][2][32];     // double-buffered h per warp
    __shared__ float cmat[4][32][33];                // output-dot transpose, padded

    const int lane = threadIdx.x & 31;
    const int wid  = threadIdx.x >> 5;
    const int b    = blockIdx.x * 4 + wid;           // 256 blocks * 4 warps = 1024

    // Lane j holds W_hh row j as 16 packed pairs
    float2 whh2[16];
    const float2* wr = reinterpret_cast<const float2*>(W_hh + lane * HH);
#pragma unroll
    for (int m = 0; m < 16; ++m) whh2[m] = wr[m];
    const float bhh  = b_hh[lane];
    const float wout = W_out[lane];
    const float bout = b_out[0];

    float h = h0[b * HH + lane];
    hs[wid][0][lane] = h;
    __syncwarp();

    const float* xpb  = g_xp + b * HH + lane;
    float* outb = out + (size_t)b * TT;

    for (int t = 0; t < TT; ++t) {
        const int cur = t & 1;
        const float xv = xpb[(size_t)t * (BB * HH)];   // coalesced per warp

        float2 a0 = {xv + bhh, 0.f}, a1 = {0.f, 0.f}, a2 = {0.f, 0.f}, a3 = {0.f, 0.f};
        const float2* hp = reinterpret_cast<const float2*>(hs[wid][cur]);
#pragma unroll
        for (int m = 0; m < 16; m += 4) {
            a0 = ffma2(hp[m + 0], whh2[m + 0], a0);
            a1 = ffma2(hp[m + 1], whh2[m + 1], a1);
            a2 = ffma2(hp[m + 2], whh2[m + 2], a2);
            a3 = ffma2(hp[m + 3], whh2[m + 3], a3);
        }
        const float s = ((a0.x + a1.x) + (a0.y + a1.y)) +
                        ((a2.x + a3.x) + (a2.y + a3.y));
        h = tanhf(s);

        hs[wid][cur ^ 1][lane]   = h;           // feed next step
        cmat[wid][t & 31][lane]  = h * wout;    // output-dot contribution
        __syncwarp();

        if ((t & 31) == 31) {
            // lane i reduces row i (steps t-31+i); stride-33 rows => conflict-free
            float s0 = 0.f, s1 = 0.f, s2 = 0.f, s3 = 0.f;
            const float* row = cmat[wid][lane];
#pragma unroll
            for (int k = 0; k < 32; k += 4) {
                s0 += row[k + 0]; s1 += row[k + 1];
                s2 += row[k + 2]; s3 += row[k + 3];
            }
            outb[(t - 31) + lane] = (s0 + s1) + (s2 + s3) + bout;  // 128B coalesced
            __syncwarp();   // protect cmat reuse next step
        }
    }

    // h_last [1, B, H] appended after outs
    out[OUT_OFFSET + b * HH + lane] = h;
}

extern "C" void kernel_launch(void* const* d_in, const int* in_sizes, int n_in,
                              void* d_out, int out_size) {
    const float* x     = (const float*)d_in[0];
    const float* h0    = (const float*)d_in[1];
    const float* W_ih  = (const float*)d_in[2];
    const float* b_ih  = (const float*)d_in[3];
    const float* W_hh  = (const float*)d_in[4];
    const float* b_hh  = (const float*)d_in[5];
    const float* W_out = (const float*)d_in[6];
    const float* b_out = (const float*)d_in[7];
    float* out = (float*)d_out;

    (void)in_sizes; (void)n_in; (void)out_size;

    xproj_kernel<<<592, 256>>>(x, W_ih, b_ih);
    rnn_kernel<<<256, 128>>>(h0, W_hh, b_hh, W_out, b_out, out);
}

// round 3
// speedup vs baseline: 1.6249x; 1.6249x over previous
#include <cuda_runtime.h>
#include <math.h>

// Problem constants
#define BB 1024
#define TT 512
#define II 64
#define HH 32
#define BBH (BB * HH)
#define OUT_OFFSET (BB * TT)      // h_last written after outs

// Scratch: x_proj in [T, B, H] layout so the recurrence reads coalesced 128B per (t,b)
__device__ float g_xp[TT * BB * HH];

// Packed fp32x2 FMA (Blackwell)
__device__ __forceinline__ float2 ffma2(float2 a, float2 b, float2 c) {
    union U { float2 f; unsigned long long u; };
    U ua, ub, uc, ud;
    ua.f = a; ub.f = b; uc.f = c;
    asm("fma.rn.f32x2 %0, %1, %2, %3;"
        : "=l"(ud.u) : "l"(ua.u), "l"(ub.u), "l"(uc.u));
    return ud.f;
}

// Fast tanh: 2 MUFU + a few ALU. |err| ~1e-6, contractive recurrence keeps
// accumulated error << 1e-3 threshold.
__device__ __forceinline__ float fast_tanh(float x) {
    float ax = fabsf(x);
    float e  = __expf(-2.0f * ax);               // MUFU.EX2 path
    float r  = __fdividef(1.0f - e, 1.0f + e);   // MUFU.RCP path
    return copysignf(r, x);
}

// ---------------------------------------------------------------------------
// Kernel 1: x_proj[t][b][h] = b_ih[h] + sum_k x[b][t][k] * W_ih[h][k]
// One warp per (b, t-quarter): streams 128 consecutive t rows (contiguous LDG),
// 4-deep smem ring prefetch, lane j owns output column j with W_ih row j in regs.
// ---------------------------------------------------------------------------
__global__ __launch_bounds__(256) void xproj_kernel(
    const float* __restrict__ x,
    const float* __restrict__ W_ih,
    const float* __restrict__ b_ih)
{
    __shared__ __align__(16) float2 sx[8][4][32];   // 8 warps, 4-deep ring

    const int lane = threadIdx.x & 31;
    const int wid  = threadIdx.x >> 5;
    const int gw   = (blockIdx.x * blockDim.x + threadIdx.x) >> 5;   // 0..4095
    const int b    = gw & 1023;
    const int t0   = (gw >> 10) * 128;                               // 0,128,256,384

    // Lane j holds W_ih row j as 32 packed pairs
    float2 w2[32];
    {
        const float2* wr = reinterpret_cast<const float2*>(W_ih + lane * II);
#pragma unroll
        for (int m = 0; m < 32; ++m) w2[m] = wr[m];
    }
    const float bias = b_ih[lane];

    const float2* xr = reinterpret_cast<const float2*>(x + ((size_t)b * TT + t0) * II);

    // Prologue: stage rows 0,1 in smem; row 2 in flight in regs
    sx[wid][0][lane] = xr[0 * 32 + lane];
    sx[wid][1][lane] = xr[1 * 32 + lane];
    float2 pre = xr[2 * 32 + lane];
    __syncwarp();

    float* gout = g_xp + (size_t)t0 * BBH + b * HH + lane;

    for (int it = 0; it < 128; ++it) {
        if (it + 2 < 128) sx[wid][(it + 2) & 3][lane] = pre;   // stage row it+2
        if (it + 3 < 128) pre = xr[(it + 3) * 32 + lane];      // prefetch row it+3
        __syncwarp();

        const float4* sp = reinterpret_cast<const float4*>(sx[wid][it & 3]);
        float2 a0 = {0.f, 0.f}, a1 = {0.f, 0.f}, a2 = {0.f, 0.f}, a3 = {0.f, 0.f};
#pragma unroll
        for (int m = 0; m < 16; m += 2) {
            float4 v0 = sp[m];
            float4 v1 = sp[m + 1];
            a0 = ffma2(make_float2(v0.x, v0.y), w2[2 * m + 0], a0);
            a1 = ffma2(make_float2(v0.z, v0.w), w2[2 * m + 1], a1);
            a2 = ffma2(make_float2(v1.x, v1.y), w2[2 * m + 2], a2);
            a3 = ffma2(make_float2(v1.z, v1.w), w2[2 * m + 3], a3);
        }
        float v = ((a0.x + a0.y) + (a1.x + a1.y)) +
                  ((a2.x + a2.y) + (a3.x + a3.y)) + bias;

        gout[(size_t)it * BBH] = v;   // 128B coalesced per warp
    }
}

// ---------------------------------------------------------------------------
// Kernel 2: sequential recurrence. One warp per batch element.
// Lane j owns h[j]; h replicated via smem double buffer (broadcast LDS.128,
// one __syncwarp per step). x_proj prefetched 8 steps ahead in a register ring.
// Per-step output dot stashed into a 33-padded smem transpose, flushed as a
// coalesced 128B store every 32 steps.
// ---------------------------------------------------------------------------
__global__ __launch_bounds__(128) void rnn_kernel(
    const float* __restrict__ h0,
    const float* __restrict__ W_hh,
    const float* __restrict__ b_hh,
    const float* __restrict__ W_out,
    const float* __restrict__ b_out,
    float* __restrict__ out)
{
    __shared__ __align__(16) float hs[4][2][32];   // double-buffered h per warp
    __shared__ float cmat[4][32][33];              // output-dot transpose, padded

    const int lane = threadIdx.x & 31;
    const int wid  = threadIdx.x >> 5;
    const int b    = blockIdx.x * 4 + wid;         // 256 blocks * 4 warps = 1024

    // Lane j holds W_hh row j as 16 packed pairs
    float2 whh2[16];
    {
        const float2* wr = reinterpret_cast<const float2*>(W_hh + lane * HH);
#pragma unroll
        for (int m = 0; m < 16; ++m) whh2[m] = wr[m];
    }
    const float bhh  = b_hh[lane];
    const float wout = W_out[lane];
    const float bout = b_out[0];

    float h = h0[b * HH + lane];
    hs[wid][0][lane] = h;
    __syncwarp();

    const float* xpb  = g_xp + b * HH + lane;
    float* outb = out + (size_t)b * TT;

    // 8-deep x_proj register prefetch ring
    float xv[8];
#pragma unroll
    for (int i = 0; i < 8; ++i) xv[i] = xpb[(size_t)i * BBH];

    for (int tb = 0; tb < TT; tb += 8) {
        float nx[8];
        if (tb + 8 < TT) {
#pragma unroll
            for (int i = 0; i < 8; ++i) nx[i] = xpb[(size_t)(tb + 8 + i) * BBH];
        } else {
#pragma unroll
            for (int i = 0; i < 8; ++i) nx[i] = 0.f;
        }

#pragma unroll
        for (int u = 0; u < 8; ++u) {
            const int t   = tb + u;
            const int cur = t & 1;

            float2 a0 = {xv[u] + bhh, 0.f};
            float2 a1 = {0.f, 0.f}, a2 = {0.f, 0.f}, a3 = {0.f, 0.f};
            const float4* hp = reinterpret_cast<const float4*>(hs[wid][cur]);
#pragma unroll
            for (int m = 0; m < 8; m += 2) {
                float4 v0 = hp[m];
                float4 v1 = hp[m + 1];
                a0 = ffma2(make_float2(v0.x, v0.y), whh2[2 * m + 0], a0);
                a1 = ffma2(make_float2(v0.z, v0.w), whh2[2 * m + 1], a1);
                a2 = ffma2(make_float2(v1.x, v1.y), whh2[2 * m + 2], a2);
                a3 = ffma2(make_float2(v1.z, v1.w), whh2[2 * m + 3], a3);
            }
            const float s = ((a0.x + a0.y) + (a1.x + a1.y)) +
                            ((a2.x + a2.y) + (a3.x + a3.y));
            h = fast_tanh(s);

            hs[wid][cur ^ 1][lane]  = h;          // feed next step
            cmat[wid][t & 31][lane] = h * wout;   // output-dot contribution
            __syncwarp();

            if (u == 7 && ((t + 1) & 31) == 0) {
                // lane i reduces row i (steps t-31+i); stride-33 rows => conflict-free
                float s0 = 0.f, s1 = 0.f, s2 = 0.f, s3 = 0.f;
                const float* row = cmat[wid][lane];
#pragma unroll
                for (int k = 0; k < 32; k += 4) {
                    s0 += row[k + 0]; s1 += row[k + 1];
                    s2 += row[k + 2]; s3 += row[k + 3];
                }
                outb[(t - 31) + lane] = (s0 + s1) + (s2 + s3) + bout;  // 128B coalesced
                __syncwarp();   // protect cmat reuse next step
            }
        }

#pragma unroll
        for (int i = 0; i < 8; ++i) xv[i] = nx[i];
    }

    // h_last [1, B, H] appended after outs
    out[OUT_OFFSET + b * HH + lane] = h;
}

extern "C" void kernel_launch(void* const* d_in, const int* in_sizes, int n_in,
                              void* d_out, int out_size) {
    const float* x     = (const float*)d_in[0];
    const float* h0    = (const float*)d_in[1];
    const float* W_ih  = (const float*)d_in[2];
    const float* b_ih  = (const float*)d_in[3];
    const float* W_hh  = (const float*)d_in[4];
    const float* b_hh  = (const float*)d_in[5];
    const float* W_out = (const float*)d_in[6];
    const float* b_out = (const float*)d_in[7];
    float* out = (float*)d_out;

    (void)in_sizes; (void)n_in; (void)out_size;

    xproj_kernel<<<512, 256>>>(x, W_ih, b_ih);
    rnn_kernel<<<256, 128>>>(h0, W_hh, b_hh, W_out, b_out, out);
}

// round 6
// speedup vs baseline: 2.9162x; 1.7947x over previous
#include <cuda_runtime.h>
#include <math.h>

// Problem constants
#define BB 1024
#define TT 512
#define II 64
#define HH 32
#define OUT_OFFSET (BB * TT)      // h_last written after outs

// Packed fp32x2 FMA / ADD (Blackwell)
__device__ __forceinline__ float2 ffma2(float2 a, float2 b, float2 c) {
    union U { float2 f; unsigned long long u; };
    U ua, ub, uc, ud;
    ua.f = a; ub.f = b; uc.f = c;
    asm("fma.rn.f32x2 %0, %1, %2, %3;"
        : "=l"(ud.u) : "l"(ua.u), "l"(ub.u), "l"(uc.u));
    return ud.f;
}
__device__ __forceinline__ float2 fadd2(float2 a, float2 b) {
    union U { float2 f; unsigned long long u; };
    U ua, ub, uc;
    ua.f = a; ub.f = b;
    asm("add.rn.f32x2 %0, %1, %2;" : "=l"(uc.u) : "l"(ua.u), "l"(ub.u));
    return uc.f;
}

// Fast tanh: tanh(x) = 1 - 2/(exp(2x)+1). ex2.approx + rcp.approx + fma.
// Saturates correctly at +-inf; |err| ~1e-6 (contractive recurrence).
__device__ __forceinline__ float fast_tanh(float x) {
    float e;
    asm("ex2.approx.f32 %0, %1;" : "=f"(e) : "f"(x * 2.885390081777927f)); // 2*log2(e)
    float r;
    asm("rcp.approx.f32 %0, %1;" : "=f"(r) : "f"(e + 1.0f));
    return fmaf(-2.0f, r, 1.0f);
}

// ---------------------------------------------------------------------------
// Fused RNN: one warp per batch element, persistent over all T=512 steps.
//  - lane j owns h[j]; W_ih row j (32 f32x2) and W_hh row j (16 f32x2) in regs
//  - x[b] rows streamed via 8-deep per-warp smem ring:
//      step t: stage row t+8 into slot t&7 (row t dead since step t-1's sync),
//              prefetch row t+12 into pre[t&3]; read row t+1 from slot (t+1)&7
//              (staged at step t-7, 7 syncwarps ago).
//  - x_proj for step t+1 computed inside step t (fills latency bubbles)
//  - h broadcast via smem double buffer, ONE __syncwarp per step
//  - output dot staged in 33-padded smem transpose, flushed every 16 steps
// Grid: 128 blocks x 256 threads = 1024 warps = 2 warps/SMSP on 128 SMs.
// ---------------------------------------------------------------------------
__global__ __launch_bounds__(256, 1) void rnn_fused_kernel(
    const float* __restrict__ x,
    const float* __restrict__ h0,
    const float* __restrict__ W_ih,
    const float* __restrict__ b_ih,
    const float* __restrict__ W_hh,
    const float* __restrict__ b_hh,
    const float* __restrict__ W_out,
    const float* __restrict__ b_out,
    float* __restrict__ out)
{
    __shared__ __align__(16) float2 sx[8][8][32];   // 8 warps, 8-row x ring
    __shared__ __align__(16) float  hs[8][2][32];   // double-buffered h
    __shared__ float cmat[8][16][33];               // output-dot transpose, padded

    const int lane = threadIdx.x & 31;
    const int wid  = threadIdx.x >> 5;
    const int b    = blockIdx.x * 8 + wid;          // 128 blocks * 8 warps = 1024

    // Weights in registers: lane j holds row j
    float2 wx[32];
    {
        const float2* wr = reinterpret_cast<const float2*>(W_ih + lane * II);
#pragma unroll
        for (int m = 0; m < 32; ++m) wx[m] = wr[m];
    }
    float2 whh[16];
    {
        const float2* wr = reinterpret_cast<const float2*>(W_hh + lane * HH);
#pragma unroll
        for (int m = 0; m < 16; ++m) whh[m] = wr[m];
    }
    const float bias = b_ih[lane] + b_hh[lane];     // folded into x_proj
    const float wout = W_out[lane];
    const float bout = b_out[0];

    const float2* xr = reinterpret_cast<const float2*>(x + (size_t)b * TT * II);
    float* outb = out + (size_t)b * TT;

    // Prologue: stage x rows 0..7 into slots 0..7; pre[i] holds row 8+i
    // (invariant: at step t, pre[t&3] holds row t+8).
#pragma unroll
    for (int i = 0; i < 8; ++i) sx[wid][i][lane] = xr[i * 32 + lane];
    float2 pre[4];
#pragma unroll
    for (int i = 0; i < 4; ++i) pre[i] = xr[(8 + i) * 32 + lane];

    float h = h0[b * HH + lane];
    hs[wid][0][lane] = h;
    __syncwarp();

    // x_proj for step 0 (row 0, slot 0)
    float xp_cur;
    {
        const float4* sp = reinterpret_cast<const float4*>(sx[wid][0]);
        float2 c0 = {bias, 0.f}, c1 = {0.f, 0.f}, c2 = {0.f, 0.f}, c3 = {0.f, 0.f};
#pragma unroll
        for (int m = 0; m < 16; m += 2) {
            float4 v0 = sp[m];
            float4 v1 = sp[m + 1];
            c0 = ffma2(make_float2(v0.x, v0.y), wx[2 * m + 0], c0);
            c1 = ffma2(make_float2(v0.z, v0.w), wx[2 * m + 1], c1);
            c2 = ffma2(make_float2(v1.x, v1.y), wx[2 * m + 2], c2);
            c3 = ffma2(make_float2(v1.z, v1.w), wx[2 * m + 3], c3);
        }
        c0 = fadd2(c0, c1); c2 = fadd2(c2, c3); c0 = fadd2(c0, c2);
        xp_cur = c0.x + c0.y;
    }

#pragma unroll 4
    for (int t = 0; t < TT; ++t) {
        // Stage row t+8 into slot t&7 (dead since step t-1's syncwarp);
        // prefetch row t+12 (clamped) into the pre ring.
        sx[wid][t & 7][lane] = pre[t & 3];
        {
            int row = t + 12; if (row > TT - 1) row = TT - 1;
            pre[t & 3] = xr[row * 32 + lane];
        }

        // --- x_proj for step t+1 (row t+1, slot (t+1)&7: staged at step t-7) ---
        const float4* sp = reinterpret_cast<const float4*>(sx[wid][(t + 1) & 7]);
        float2 c0 = {bias, 0.f}, c1 = {0.f, 0.f}, c2 = {0.f, 0.f}, c3 = {0.f, 0.f};
#pragma unroll
        for (int m = 0; m < 16; m += 2) {
            float4 v0 = sp[m];
            float4 v1 = sp[m + 1];
            c0 = ffma2(make_float2(v0.x, v0.y), wx[2 * m + 0], c0);
            c1 = ffma2(make_float2(v0.z, v0.w), wx[2 * m + 1], c1);
            c2 = ffma2(make_float2(v1.x, v1.y), wx[2 * m + 2], c2);
            c3 = ffma2(make_float2(v1.z, v1.w), wx[2 * m + 3], c3);
        }
        c0 = fadd2(c0, c1); c2 = fadd2(c2, c3); c0 = fadd2(c0, c2);
        const float xp_next = c0.x + c0.y;

        // --- recurrence: s = xp_cur + W_hh . h ---
        const float4* hp = reinterpret_cast<const float4*>(hs[wid][t & 1]);
        float2 a0 = {xp_cur, 0.f}, a1 = {0.f, 0.f}, a2 = {0.f, 0.f}, a3 = {0.f, 0.f};
#pragma unroll
        for (int m = 0; m < 8; m += 2) {
            float4 v0 = hp[m];
            float4 v1 = hp[m + 1];
            a0 = ffma2(make_float2(v0.x, v0.y), whh[2 * m + 0], a0);
            a1 = ffma2(make_float2(v0.z, v0.w), whh[2 * m + 1], a1);
            a2 = ffma2(make_float2(v1.x, v1.y), whh[2 * m + 2], a2);
            a3 = ffma2(make_float2(v1.z, v1.w), whh[2 * m + 3], a3);
        }
        a0 = fadd2(a0, a1); a2 = fadd2(a2, a3); a0 = fadd2(a0, a2);
        h = fast_tanh(a0.x + a0.y);

        hs[wid][(t + 1) & 1][lane] = h;        // feed next step
        cmat[wid][t & 15][lane]    = h * wout; // output-dot contribution
        __syncwarp();

        if ((t & 15) == 15) {
            // 16 outputs; 2 lanes per output (halves), stride-33 rows => conflict-free
            const int tt = lane & 15, hf = lane >> 4;
            const float* row = &cmat[wid][tt][hf * 16];
            float s0 = 0.f, s1 = 0.f, s2 = 0.f, s3 = 0.f;
#pragma unroll
            for (int k = 0; k < 16; k += 4) {
                s0 += row[k + 0]; s1 += row[k + 1];
                s2 += row[k + 2]; s3 += row[k + 3];
            }
            float v = (s0 + s1) + (s2 + s3);
            v += __shfl_down_sync(0xffffffffu, v, 16);
            if (lane < 16) outb[t - 15 + lane] = v + bout;  // 64B coalesced
            __syncwarp();   // protect cmat reuse next step
        }

        xp_cur = xp_next;
    }

    // h_last [1, B, H] appended after outs
    out[OUT_OFFSET + b * HH + lane] = h;
}

extern "C" void kernel_launch(void* const* d_in, const int* in_sizes, int n_in,
                              void* d_out, int out_size) {
    const float* x     = (const float*)d_in[0];
    const float* h0    = (const float*)d_in[1];
    const float* W_ih  = (const float*)d_in[2];
    const float* b_ih  = (const float*)d_in[3];
    const float* W_hh  = (const float*)d_in[4];
    const float* b_hh  = (const float*)d_in[5];
    const float* W_out = (const float*)d_in[6];
    const float* b_out = (const float*)d_in[7];
    float* out = (float*)d_out;

    (void)in_sizes; (void)n_in; (void)out_size;

    rnn_fused_kernel<<<128, 256>>>(x, h0, W_ih, b_ih, W_hh, b_hh, W_out, b_out, out);
}